// round 13
// baseline (speedup 1.0000x reference)
#include <cuda_runtime.h>
#include <cuda_fp16.h>
#include <math.h>

#define N_NODES 50000
#define N_EDGES 1600000
#define BATCH   2
#define C       64
#define CAP     192
#define NBLK    ((N_NODES + 255) / 256)

// ---- scratch ----
__device__ int    g_cnt[N_NODES];
__device__ int    g_cursor[N_NODES];
__device__ float  g_dis[N_NODES];
__device__ float2 g_nf[N_NODES];      // {flux_b0, flux_b1}
// interleaved per (batch,node) row: [dis_n*xc: 64 halfs][dis_n*xd: 64 halfs]
__device__ __align__(16) __half g_xi[(size_t)BATCH * N_NODES * 2 * C];
// fixed-capacity buckets: slot = tgt*CAP + k ; {src(int bits), fb0, fb1, pad}
__device__ float4 g_em[(size_t)N_NODES * CAP];
__device__ int    g_is64;

// ---- packed f32x2 helpers ----
__device__ __forceinline__ unsigned long long pk2(float x, float y) {
    unsigned long long r;
    asm("mov.b64 %0, {%1,%2};" : "=l"(r) : "f"(x), "f"(y));
    return r;
}
__device__ __forceinline__ void upk2(unsigned long long v, float& x, float& y) {
    asm("mov.b64 {%0,%1}, %2;" : "=f"(x), "=f"(y) : "l"(v));
}
__device__ __forceinline__ void fma2(unsigned long long& c,
                                     unsigned long long a,
                                     unsigned long long b) {
    asm("fma.rn.f32x2 %0, %1, %2, %0;" : "+l"(c) : "l"(a), "l"(b));
}
__device__ __forceinline__ void add2(unsigned long long& c, unsigned long long a) {
    asm("add.rn.f32x2 %0, %0, %1;" : "+l"(c) : "l"(a));
}
__device__ __forceinline__ float tanh_fast(float x) {
    asm("tanh.approx.f32 %0, %0;" : "+f"(x));
    return x;
}

// ---------------------------------------------------------------------------
// detect dtype + zero counters + build flux pairs (all independent of edges)
// ---------------------------------------------------------------------------
__global__ void detect_init_kernel(const unsigned int* __restrict__ w,
                                   const float* __restrict__ fluxes) {
    int i = blockIdx.x * blockDim.x + threadIdx.x;
    if (i < N_NODES) {
        g_cnt[i] = 0;
        g_cursor[i] = 0;
        g_nf[i] = make_float2(fluxes[i], fluxes[N_NODES + i]);
    }
    if (blockIdx.x == 0) {
        __shared__ unsigned int acc;
        if (threadIdx.x == 0) acc = 0u;
        __syncthreads();
        unsigned int v = 0u;
        for (int j = threadIdx.x; j < 4096; j += blockDim.x)
            v |= w[(size_t)2 * j * 97 + 1];
        atomicOr(&acc, v);
        __syncthreads();
        if (threadIdx.x == 0) g_is64 = (acc == 0u) ? 1 : 0;
    }
}

__device__ __forceinline__ int load_idx(const int* __restrict__ ei, size_t e) {
    return g_is64 ? ei[2 * e] : ei[e];
}

// 4 edges per thread
__global__ void hist_kernel(const int* __restrict__ ei) {
    int e4 = (blockIdx.x * blockDim.x + threadIdx.x) * 4;
    if (e4 >= N_EDGES) return;
    int t0, t1, t2, t3;
    if (g_is64) {
        const int4 v0 = *(const int4*)(ei + 2 * ((size_t)N_EDGES + e4));
        const int4 v1 = *(const int4*)(ei + 2 * ((size_t)N_EDGES + e4) + 4);
        t0 = v0.x; t1 = v0.z; t2 = v1.x; t3 = v1.z;
    } else {
        const int4 v = *(const int4*)(ei + (size_t)N_EDGES + e4);
        t0 = v.x; t1 = v.y; t2 = v.z; t3 = v.w;
    }
    atomicAdd(&g_cnt[t0], 1);
    atomicAdd(&g_cnt[t1], 1);
    atomicAdd(&g_cnt[t2], 1);
    atomicAdd(&g_cnt[t3], 1);
}

__global__ void dis_kernel() {
    int i = blockIdx.x * blockDim.x + threadIdx.x;
    if (i < N_NODES) g_dis[i] = rsqrtf((float)(g_cnt[i] + 1));
}

// ---------------------------------------------------------------------------
// fill buckets (independent of degrees!): meta = {src, fb0, fb1, 0}.
// 2 edges per thread.
// ---------------------------------------------------------------------------
__global__ void __launch_bounds__(256)
fill_kernel(const int* __restrict__ ei,
            const float* __restrict__ fdo) {
    int e = (blockIdx.x * blockDim.x + threadIdx.x) * 2;
    if (e >= N_EDGES) return;

    int s0, s1, t0, t1;
    if (g_is64) {
        const int4 vs = *(const int4*)(ei + 2 * (size_t)e);
        const int4 vt = *(const int4*)(ei + 2 * ((size_t)N_EDGES + e));
        s0 = vs.x; s1 = vs.z; t0 = vt.x; t1 = vt.z;
    } else {
        const int2 vs = *(const int2*)(ei + (size_t)e);
        const int2 vt = *(const int2*)(ei + (size_t)N_EDGES + e);
        s0 = vs.x; s1 = vs.y; t0 = vt.x; t1 = vt.y;
    }
    const float2 f01 = *(const float2*)(fdo + e);

#pragma unroll
    for (int k = 0; k < 2; k++) {
        const int   s  = k ? s1 : s0;
        const int   t  = k ? t1 : t0;
        const float f0 = k ? f01.y : f01.x;

        const float2 nfs = __ldg(&g_nf[s]);
        const float2 nft = __ldg(&g_nf[t]);

        const float k0 = 0.5f * (1.0f + tanh_fast(nfs.x * nft.x));
        const float k1 = 0.5f * (1.0f + tanh_fast(nfs.y * nft.y));
        const float fb0 = k0 * f0 + (1.0f - k0) * (1.0f - f0);
        const float fb1 = k1 * f0 + (1.0f - k1) * (1.0f - f0);

        const int pos = t * CAP + atomicAdd(&g_cursor[t], 1);
        g_em[pos] = make_float4(__int_as_float(s), fb0, fb1, 0.0f);
    }
}

// ---------------------------------------------------------------------------
// Dual GEMM -> interleaved fp16 rows scaled by dis[node]. FFMA2-packed.
// ---------------------------------------------------------------------------
__global__ void __launch_bounds__(256)
gemm_kernel(const float* __restrict__ x,
            const float* __restrict__ Wc,
            const float* __restrict__ Wd) {
    const int o  = threadIdx.x >> 2;
    const int kg = threadIdx.x & 3;

    unsigned long long wp[16];
#pragma unroll
    for (int i = 0; i < 16; i++)
        wp[i] = pk2(Wc[o * C + kg * 16 + i], Wd[o * C + kg * 16 + i]);

    __shared__ __align__(16) float xs[4][C];
    const int M = BATCH * N_NODES;
    const int lr = threadIdx.x >> 6;
    const int lc = threadIdx.x & 63;

    for (int m0 = blockIdx.x * 4; m0 < M; m0 += gridDim.x * 4) {
        __syncthreads();
        xs[lr][lc] = x[(size_t)(m0 + lr) * C + lc];
        __syncthreads();

#pragma unroll
        for (int r2 = 0; r2 < 4; r2++) {
            const float4* xp = (const float4*)&xs[r2][kg * 16];
            unsigned long long acc = 0ull;
#pragma unroll
            for (int j = 0; j < 4; j++) {
                float4 xv = xp[j];
                fma2(acc, pk2(xv.x, xv.x), wp[4 * j + 0]);
                fma2(acc, pk2(xv.y, xv.y), wp[4 * j + 1]);
                fma2(acc, pk2(xv.z, xv.z), wp[4 * j + 2]);
                fma2(acc, pk2(xv.w, xv.w), wp[4 * j + 3]);
            }
            float sc, sd;
            upk2(acc, sc, sd);
            sc += __shfl_xor_sync(0xffffffffu, sc, 1);
            sc += __shfl_xor_sync(0xffffffffu, sc, 2);
            sd += __shfl_xor_sync(0xffffffffu, sd, 1);
            sd += __shfl_xor_sync(0xffffffffu, sd, 2);
            float sc2 = __shfl_xor_sync(0xffffffffu, sc, 4);
            float sd2 = __shfl_xor_sync(0xffffffffu, sd, 4);

            if (kg == 0 && (o & 1) == 0) {
                const int m = m0 + r2;
                const int n = (m >= N_NODES) ? (m - N_NODES) : m;
                const float dv = __ldg(&g_dis[n]);     // fold dis_src into row
                __half* row = g_xi + (size_t)m * (2 * C);
                *(__half2*)(row + o)     = __floats2half2_rn(dv * sc, dv * sc2);
                *(__half2*)(row + C + o) = __floats2half2_rn(dv * sd, dv * sd2);
            }
        }
    }
}

// ---------------------------------------------------------------------------
// Gather: smem-staged meta; coefficients (1-fb, fb); dis_t applied ONCE after
// reduction (uniform per warp). Self-loop = own scaled row with coeff 1.
// out = bias + dis_t * acc.
// ---------------------------------------------------------------------------
__global__ void __launch_bounds__(128, 6)
gather_kernel(const float* __restrict__ bias, float* __restrict__ out) {
    __shared__ __align__(16) float4 smeta[4][CAP];   // 12 KB / block

    const int w = (int)((blockIdx.x * blockDim.x + threadIdx.x) >> 5);
    if (w >= BATCH * N_NODES) return;
    const int b    = (w < N_NODES) ? 0 : 1;
    const int n    = (w < N_NODES) ? w : (w - N_NODES);
    const int lane = threadIdx.x & 31;
    const int g    = lane >> 3;        // edge group 0..3
    const int l8   = lane & 7;         // 8 channels: l8*8 .. +8

    const int cnt = g_cnt[n];
    const int beg = n * CAP;
    float4* sm = smeta[threadIdx.x >> 5];

    for (int j = lane; j < cnt; j += 32)
        sm[j] = __ldg(&g_em[beg + j]);
    __syncwarp();

    const __half*  __restrict__ xib = g_xi + (size_t)b * N_NODES * (2 * C);

    unsigned long long a0 = 0ull, a1 = 0ull, a2 = 0ull, a3 = 0ull;

    if (g == 0) {   // self-loop: own (dis-scaled) xc row, coefficient 1
        const uint4 xh = *(const uint4*)(xib + (size_t)n * (2 * C) + l8 * 8);
        const float2 x0 = __half22float2(*(const __half2*)&xh.x);
        const float2 x1 = __half22float2(*(const __half2*)&xh.y);
        const float2 x2 = __half22float2(*(const __half2*)&xh.z);
        const float2 x3 = __half22float2(*(const __half2*)&xh.w);
        a0 = pk2(x0.x, x0.y);
        a1 = pk2(x1.x, x1.y);
        a2 = pk2(x2.x, x2.y);
        a3 = pk2(x3.x, x3.y);
    }

    int e = g;                         // this group's slots: e, e+4, e+8, e+12
    if (e < cnt) {
        float3 m[4];
#pragma unroll
        for (int k = 0; k < 4; k++) {
            const int  j = e + 4 * k;
            const bool v = (j < cnt);
            const float4 t = sm[v ? j : 0];
            const float fb = v ? (b ? t.z : t.y) : 0.0f;
            m[k] = make_float3(t.x, v ? (1.0f - fb) : 0.0f, fb);
        }

        for (;;) {
            uint4 A[4], D[4];
#pragma unroll
            for (int k = 0; k < 4; k++) {
                const __half* row = xib +
                    (size_t)__float_as_int(m[k].x) * (2 * C) + l8 * 8;
                A[k] = __ldg((const uint4*)(row));
                D[k] = __ldg((const uint4*)(row + C));
            }

            e += 16;
            const bool more = (e < cnt);
            float3 mn[4];
#pragma unroll
            for (int k = 0; k < 4; k++) {
                const int  j = e + 4 * k;
                const bool v = (j < cnt);
                const float4 t = sm[v ? j : 0];
                const float fb = v ? (b ? t.z : t.y) : 0.0f;
                mn[k] = make_float3(t.x, v ? (1.0f - fb) : 0.0f, fb);
            }

#pragma unroll
            for (int p = 0; p < 2; p++) {
                const int k0 = 2 * p, k1 = 2 * p + 1;
                const __half2 cc0 = __float2half2_rn(m[k0].y);
                const __half2 cd0 = __float2half2_rn(m[k0].z);
                const __half2 cc1 = __float2half2_rn(m[k1].y);
                const __half2 cd1 = __float2half2_rn(m[k1].z);
                const __half2* A0 = (const __half2*)&A[k0];
                const __half2* D0 = (const __half2*)&D[k0];
                const __half2* A1 = (const __half2*)&A[k1];
                const __half2* D1 = (const __half2*)&D[k1];

                __half2 h0 = __hmul2(A0[0], cc0);
                __half2 h1 = __hmul2(A0[1], cc0);
                __half2 h2 = __hmul2(A0[2], cc0);
                __half2 h3 = __hmul2(A0[3], cc0);
                h0 = __hfma2(D0[0], cd0, h0);
                h1 = __hfma2(D0[1], cd0, h1);
                h2 = __hfma2(D0[2], cd0, h2);
                h3 = __hfma2(D0[3], cd0, h3);
                h0 = __hfma2(A1[0], cc1, h0);
                h1 = __hfma2(A1[1], cc1, h1);
                h2 = __hfma2(A1[2], cc1, h2);
                h3 = __hfma2(A1[3], cc1, h3);
                h0 = __hfma2(D1[0], cd1, h0);
                h1 = __hfma2(D1[1], cd1, h1);
                h2 = __hfma2(D1[2], cd1, h2);
                h3 = __hfma2(D1[3], cd1, h3);

                float2 f;
                f = __half22float2(h0); add2(a0, pk2(f.x, f.y));
                f = __half22float2(h1); add2(a1, pk2(f.x, f.y));
                f = __half22float2(h2); add2(a2, pk2(f.x, f.y));
                f = __half22float2(h3); add2(a3, pk2(f.x, f.y));
            }

            if (!more) break;
#pragma unroll
            for (int k = 0; k < 4; k++) m[k] = mn[k];
        }
    }

    // reduce the 4 groups
    float f0, f1, f2, f3, f4, f5, f6, f7;
    upk2(a0, f0, f1); upk2(a1, f2, f3); upk2(a2, f4, f5); upk2(a3, f6, f7);
#pragma unroll
    for (int d = 8; d <= 16; d <<= 1) {
        f0 += __shfl_xor_sync(0xffffffffu, f0, d);
        f1 += __shfl_xor_sync(0xffffffffu, f1, d);
        f2 += __shfl_xor_sync(0xffffffffu, f2, d);
        f3 += __shfl_xor_sync(0xffffffffu, f3, d);
        f4 += __shfl_xor_sync(0xffffffffu, f4, d);
        f5 += __shfl_xor_sync(0xffffffffu, f5, d);
        f6 += __shfl_xor_sync(0xffffffffu, f6, d);
        f7 += __shfl_xor_sync(0xffffffffu, f7, d);
    }

    if (g == 0) {
        const float dv = g_dis[n];     // dis_t, uniform per warp
        const float4 b0 = *(const float4*)(bias + l8 * 8);
        const float4 b1 = *(const float4*)(bias + l8 * 8 + 4);
        float* orow = out + ((size_t)b * N_NODES + n) * C + l8 * 8;
        *(float4*)(orow)     = make_float4(fmaf(dv, f0, b0.x), fmaf(dv, f1, b0.y),
                                           fmaf(dv, f2, b0.z), fmaf(dv, f3, b0.w));
        *(float4*)(orow + 4) = make_float4(fmaf(dv, f4, b1.x), fmaf(dv, f5, b1.y),
                                           fmaf(dv, f6, b1.z), fmaf(dv, f7, b1.w));
    }
}

// ---------------------------------------------------------------------------
extern "C" void kernel_launch(void* const* d_in, const int* in_sizes, int n_in,
                              void* d_out, int out_size) {
    const float* x    = (const float*)d_in[0];
    const int*   ei   = (const int*)d_in[1];
    const float* fdo  = (const float*)d_in[2];
    const float* flux = (const float*)d_in[3];
    const float* Wc   = (const float*)d_in[4];
    const float* Wd   = (const float*)d_in[5];
    const float* bias = (const float*)d_in[6];
    float* out = (float*)d_out;

    static cudaStream_t s2 = nullptr;
    static cudaEvent_t evFork = nullptr, evJoin = nullptr;
    if (!s2) {
        cudaStreamCreateWithFlags(&s2, cudaStreamNonBlocking);
        cudaEventCreateWithFlags(&evFork, cudaEventDisableTiming);
        cudaEventCreateWithFlags(&evJoin, cudaEventDisableTiming);
    }

    // main: detect -> hist -> dis -> gemm(dis-scaled)
    detect_init_kernel<<<NBLK, 256>>>((const unsigned int*)ei, flux);
    cudaEventRecord(evFork, 0);

    // s2: fill (needs only detect outputs)
    cudaStreamWaitEvent(s2, evFork, 0);
    fill_kernel<<<(N_EDGES / 2 + 255) / 256, 256, 0, s2>>>(ei, fdo);
    cudaEventRecord(evJoin, s2);

    hist_kernel<<<(N_EDGES / 4 + 255) / 256, 256>>>(ei);
    dis_kernel<<<NBLK, 256>>>();
    gemm_kernel<<<2960, 256>>>(x, Wc, Wd);

    // join, then gather
    cudaStreamWaitEvent(0, evJoin, 0);
    gather_kernel<<<(BATCH * N_NODES * 32 + 127) / 128, 128>>>(bias, out);
}

// round 14
// speedup vs baseline: 1.0356x; 1.0356x over previous
#include <cuda_runtime.h>
#include <cuda_fp16.h>
#include <math.h>

#define N_NODES 50000
#define N_EDGES 1600000
#define BATCH   2
#define C       64
#define CAP     192
#define NBLK    ((N_NODES + 255) / 256)

// ---- scratch ----
__device__ int    g_cnt[N_NODES];
__device__ int    g_cursor[N_NODES];
__device__ float4 g_ni[N_NODES];      // {flux_b0, flux_b1, dis, 0}
// interleaved per (batch,node) row: [xc: 64 halfs][xd: 64 halfs] = 256 B
__device__ __align__(16) __half g_xi[(size_t)BATCH * N_NODES * 2 * C];
// packed 8B meta: w0 = src(u16) | fb0(half)<<16 ; w1 = norm(half) | fb1(half)<<16
__device__ uint2  g_em[(size_t)N_NODES * CAP];
__device__ int    g_is64;

// ---- packed f32x2 helpers ----
__device__ __forceinline__ unsigned long long pk2(float x, float y) {
    unsigned long long r;
    asm("mov.b64 %0, {%1,%2};" : "=l"(r) : "f"(x), "f"(y));
    return r;
}
__device__ __forceinline__ void upk2(unsigned long long v, float& x, float& y) {
    asm("mov.b64 {%0,%1}, %2;" : "=f"(x), "=f"(y) : "l"(v));
}
__device__ __forceinline__ void fma2(unsigned long long& c,
                                     unsigned long long a,
                                     unsigned long long b) {
    asm("fma.rn.f32x2 %0, %1, %2, %0;" : "+l"(c) : "l"(a), "l"(b));
}
__device__ __forceinline__ void add2(unsigned long long& c, unsigned long long a) {
    asm("add.rn.f32x2 %0, %0, %1;" : "+l"(c) : "l"(a));
}
__device__ __forceinline__ float tanh_fast(float x) {
    asm("tanh.approx.f32 %0, %0;" : "+f"(x));
    return x;
}

// ---------------------------------------------------------------------------
__global__ void detect_zero_kernel(const unsigned int* __restrict__ w) {
    int i = blockIdx.x * blockDim.x + threadIdx.x;
    if (i < N_NODES) { g_cnt[i] = 0; g_cursor[i] = 0; }
    if (blockIdx.x == 0) {
        __shared__ unsigned int acc;
        if (threadIdx.x == 0) acc = 0u;
        __syncthreads();
        unsigned int v = 0u;
        for (int j = threadIdx.x; j < 4096; j += blockDim.x)
            v |= w[(size_t)2 * j * 97 + 1];
        atomicOr(&acc, v);
        __syncthreads();
        if (threadIdx.x == 0) g_is64 = (acc == 0u) ? 1 : 0;
    }
}

// 4 edges per thread
__global__ void hist_kernel(const int* __restrict__ ei) {
    int e4 = (blockIdx.x * blockDim.x + threadIdx.x) * 4;
    if (e4 >= N_EDGES) return;
    int t0, t1, t2, t3;
    if (g_is64) {
        const int4 v0 = *(const int4*)(ei + 2 * ((size_t)N_EDGES + e4));
        const int4 v1 = *(const int4*)(ei + 2 * ((size_t)N_EDGES + e4) + 4);
        t0 = v0.x; t1 = v0.z; t2 = v1.x; t3 = v1.z;
    } else {
        const int4 v = *(const int4*)(ei + (size_t)N_EDGES + e4);
        t0 = v.x; t1 = v.y; t2 = v.z; t3 = v.w;
    }
    atomicAdd(&g_cnt[t0], 1);
    atomicAdd(&g_cnt[t1], 1);
    atomicAdd(&g_cnt[t2], 1);
    atomicAdd(&g_cnt[t3], 1);
}

// node info: dis from degree + fluxes
__global__ void ni_kernel(const float* __restrict__ fluxes) {
    int i = blockIdx.x * blockDim.x + threadIdx.x;
    if (i < N_NODES) {
        const float dis = rsqrtf((float)(g_cnt[i] + 1));
        g_ni[i] = make_float4(fluxes[i], fluxes[N_NODES + i], dis, 0.0f);
    }
}

// ---------------------------------------------------------------------------
// fill: 2 edges/thread; packed 8B meta per edge (serves both batches).
// ---------------------------------------------------------------------------
__global__ void __launch_bounds__(256)
fill_kernel(const int* __restrict__ ei,
            const float* __restrict__ fdo) {
    int e = (blockIdx.x * blockDim.x + threadIdx.x) * 2;
    if (e >= N_EDGES) return;

    int s0, s1, t0, t1;
    if (g_is64) {
        const int4 vs = *(const int4*)(ei + 2 * (size_t)e);
        const int4 vt = *(const int4*)(ei + 2 * ((size_t)N_EDGES + e));
        s0 = vs.x; s1 = vs.z; t0 = vt.x; t1 = vt.z;
    } else {
        const int2 vs = *(const int2*)(ei + (size_t)e);
        const int2 vt = *(const int2*)(ei + (size_t)N_EDGES + e);
        s0 = vs.x; s1 = vs.y; t0 = vt.x; t1 = vt.y;
    }
    const float2 f01 = *(const float2*)(fdo + e);

#pragma unroll
    for (int k = 0; k < 2; k++) {
        const int   s  = k ? s1 : s0;
        const int   t  = k ? t1 : t0;
        const float f0 = k ? f01.y : f01.x;

        const float4 nis = __ldg(&g_ni[s]);
        const float4 nit = __ldg(&g_ni[t]);

        const float norm = nis.z * nit.z;
        const float k0 = 0.5f * (1.0f + tanh_fast(nis.x * nit.x));
        const float k1 = 0.5f * (1.0f + tanh_fast(nis.y * nit.y));
        const float fb0 = k0 * f0 + (1.0f - k0) * (1.0f - f0);
        const float fb1 = k1 * f0 + (1.0f - k1) * (1.0f - f0);

        const unsigned w0 = (unsigned)s |
            ((unsigned)__half_as_ushort(__float2half_rn(fb0)) << 16);
        const unsigned w1 = (unsigned)__half_as_ushort(__float2half_rn(norm)) |
            ((unsigned)__half_as_ushort(__float2half_rn(fb1)) << 16);

        const int pos = t * CAP + atomicAdd(&g_cursor[t], 1);
        g_em[pos] = make_uint2(w0, w1);
    }
}

// ---------------------------------------------------------------------------
// Dual GEMM -> interleaved fp16 rows [xc(64)|xd(64)]. FFMA2-packed.
// Fully independent of the edge chain (forked stream).
// ---------------------------------------------------------------------------
__global__ void __launch_bounds__(256)
gemm_kernel(const float* __restrict__ x,
            const float* __restrict__ Wc,
            const float* __restrict__ Wd) {
    const int o  = threadIdx.x >> 2;
    const int kg = threadIdx.x & 3;

    unsigned long long wp[16];
#pragma unroll
    for (int i = 0; i < 16; i++)
        wp[i] = pk2(Wc[o * C + kg * 16 + i], Wd[o * C + kg * 16 + i]);

    __shared__ __align__(16) float xs[4][C];
    const int M = BATCH * N_NODES;
    const int lr = threadIdx.x >> 6;
    const int lc = threadIdx.x & 63;

    for (int m0 = blockIdx.x * 4; m0 < M; m0 += gridDim.x * 4) {
        __syncthreads();
        xs[lr][lc] = x[(size_t)(m0 + lr) * C + lc];
        __syncthreads();

#pragma unroll
        for (int r2 = 0; r2 < 4; r2++) {
            const float4* xp = (const float4*)&xs[r2][kg * 16];
            unsigned long long acc = 0ull;
#pragma unroll
            for (int j = 0; j < 4; j++) {
                float4 xv = xp[j];
                fma2(acc, pk2(xv.x, xv.x), wp[4 * j + 0]);
                fma2(acc, pk2(xv.y, xv.y), wp[4 * j + 1]);
                fma2(acc, pk2(xv.z, xv.z), wp[4 * j + 2]);
                fma2(acc, pk2(xv.w, xv.w), wp[4 * j + 3]);
            }
            float sc, sd;
            upk2(acc, sc, sd);
            sc += __shfl_xor_sync(0xffffffffu, sc, 1);
            sc += __shfl_xor_sync(0xffffffffu, sc, 2);
            sd += __shfl_xor_sync(0xffffffffu, sd, 1);
            sd += __shfl_xor_sync(0xffffffffu, sd, 2);
            float sc2 = __shfl_xor_sync(0xffffffffu, sc, 4);
            float sd2 = __shfl_xor_sync(0xffffffffu, sd, 4);

            if (kg == 0 && (o & 1) == 0) {
                __half* row = g_xi + (size_t)(m0 + r2) * (2 * C);
                *(__half2*)(row + o)     = __floats2half2_rn(sc, sc2);
                *(__half2*)(row + C + o) = __floats2half2_rn(sd, sd2);
            }
        }
    }
}

// ---------------------------------------------------------------------------
// Gather (R12 structure, 8B meta): smem-staged bucket meta; one warp per
// (node,batch); four 8-lane groups x 4 edges/trip; rows via LDG.128;
// fp16 core, f32x2 flush; self-loop coeff = 1/deg = dis^2.
// ---------------------------------------------------------------------------
__global__ void __launch_bounds__(128, 6)
gather_kernel(const float* __restrict__ bias, float* __restrict__ out) {
    __shared__ __align__(16) uint2 smeta[4][CAP];   // 6 KB / block

    const int w = (int)((blockIdx.x * blockDim.x + threadIdx.x) >> 5);
    if (w >= BATCH * N_NODES) return;
    const int b    = (w < N_NODES) ? 0 : 1;
    const int n    = (w < N_NODES) ? w : (w - N_NODES);
    const int lane = threadIdx.x & 31;
    const int g    = lane >> 3;        // edge group 0..3
    const int l8   = lane & 7;         // 8 channels: l8*8 .. +8

    const int cnt = g_cnt[n];
    const int beg = n * CAP;
    uint2* sm = smeta[threadIdx.x >> 5];

    for (int j = lane; j < cnt; j += 32)
        sm[j] = __ldg(&g_em[beg + j]);
    __syncwarp();

    const __half*  __restrict__ xib = g_xi + (size_t)b * N_NODES * (2 * C);

    unsigned long long a0 = 0ull, a1 = 0ull, a2 = 0ull, a3 = 0ull;

    if (g == 0) {   // self-loop + bias init
        const float4 ni = g_ni[n];
        const float nrm = ni.z * ni.z;
        const float4 b0 = *(const float4*)(bias + l8 * 8);
        const float4 b1 = *(const float4*)(bias + l8 * 8 + 4);
        const uint4  xh = *(const uint4*)(xib + (size_t)n * (2 * C) + l8 * 8);
        const float2 x0 = __half22float2(*(const __half2*)&xh.x);
        const float2 x1 = __half22float2(*(const __half2*)&xh.y);
        const float2 x2 = __half22float2(*(const __half2*)&xh.z);
        const float2 x3 = __half22float2(*(const __half2*)&xh.w);
        a0 = pk2(fmaf(nrm, x0.x, b0.x), fmaf(nrm, x0.y, b0.y));
        a1 = pk2(fmaf(nrm, x1.x, b0.z), fmaf(nrm, x1.y, b0.w));
        a2 = pk2(fmaf(nrm, x2.x, b1.x), fmaf(nrm, x2.y, b1.y));
        a3 = pk2(fmaf(nrm, x3.x, b1.z), fmaf(nrm, x3.y, b1.w));
    }

    // meta decode: w0 = src | fb0h<<16 ; w1 = normh | fb1h<<16
    auto decode = [&](int j, bool v) -> float3 {
        const uint2 t = sm[v ? j : 0];
        const float2 nf1 = __half22float2(*(const __half2*)&t.y); // (norm, fb1)
        const float2 jf0 = __half22float2(*(const __half2*)&t.x); // (junk, fb0)
        const float fb   = b ? nf1.y : jf0.y;
        const float cD   = v ? nf1.x * fb : 0.0f;
        const float cC   = v ? nf1.x - cD : 0.0f;
        return make_float3(__int_as_float((int)(t.x & 0xFFFFu)), cC, cD);
    };

    int e = g;                         // this group's slots: e, e+4, e+8, e+12
    if (e < cnt) {
        float3 m[4];
#pragma unroll
        for (int k = 0; k < 4; k++) {
            const int j = e + 4 * k;
            m[k] = decode(j, j < cnt);
        }

        for (;;) {
            uint4 A[4], D[4];
#pragma unroll
            for (int k = 0; k < 4; k++) {
                const __half* row = xib +
                    (size_t)__float_as_int(m[k].x) * (2 * C) + l8 * 8;
                A[k] = __ldg((const uint4*)(row));
                D[k] = __ldg((const uint4*)(row + C));
            }

            e += 16;
            const bool more = (e < cnt);
            float3 mn[4];
#pragma unroll
            for (int k = 0; k < 4; k++) {
                const int j = e + 4 * k;
                mn[k] = decode(j, j < cnt);
            }

#pragma unroll
            for (int p = 0; p < 2; p++) {
                const int k0 = 2 * p, k1 = 2 * p + 1;
                const __half2 cc0 = __float2half2_rn(m[k0].y);
                const __half2 cd0 = __float2half2_rn(m[k0].z);
                const __half2 cc1 = __float2half2_rn(m[k1].y);
                const __half2 cd1 = __float2half2_rn(m[k1].z);
                const __half2* A0 = (const __half2*)&A[k0];
                const __half2* D0 = (const __half2*)&D[k0];
                const __half2* A1 = (const __half2*)&A[k1];
                const __half2* D1 = (const __half2*)&D[k1];

                __half2 h0 = __hmul2(A0[0], cc0);
                __half2 h1 = __hmul2(A0[1], cc0);
                __half2 h2 = __hmul2(A0[2], cc0);
                __half2 h3 = __hmul2(A0[3], cc0);
                h0 = __hfma2(D0[0], cd0, h0);
                h1 = __hfma2(D0[1], cd0, h1);
                h2 = __hfma2(D0[2], cd0, h2);
                h3 = __hfma2(D0[3], cd0, h3);
                h0 = __hfma2(A1[0], cc1, h0);
                h1 = __hfma2(A1[1], cc1, h1);
                h2 = __hfma2(A1[2], cc1, h2);
                h3 = __hfma2(A1[3], cc1, h3);
                h0 = __hfma2(D1[0], cd1, h0);
                h1 = __hfma2(D1[1], cd1, h1);
                h2 = __hfma2(D1[2], cd1, h2);
                h3 = __hfma2(D1[3], cd1, h3);

                float2 f;
                f = __half22float2(h0); add2(a0, pk2(f.x, f.y));
                f = __half22float2(h1); add2(a1, pk2(f.x, f.y));
                f = __half22float2(h2); add2(a2, pk2(f.x, f.y));
                f = __half22float2(h3); add2(a3, pk2(f.x, f.y));
            }

            if (!more) break;
#pragma unroll
            for (int k = 0; k < 4; k++) m[k] = mn[k];
        }
    }

    // reduce the 4 groups
    float f0, f1, f2, f3, f4, f5, f6, f7;
    upk2(a0, f0, f1); upk2(a1, f2, f3); upk2(a2, f4, f5); upk2(a3, f6, f7);
#pragma unroll
    for (int d = 8; d <= 16; d <<= 1) {
        f0 += __shfl_xor_sync(0xffffffffu, f0, d);
        f1 += __shfl_xor_sync(0xffffffffu, f1, d);
        f2 += __shfl_xor_sync(0xffffffffu, f2, d);
        f3 += __shfl_xor_sync(0xffffffffu, f3, d);
        f4 += __shfl_xor_sync(0xffffffffu, f4, d);
        f5 += __shfl_xor_sync(0xffffffffu, f5, d);
        f6 += __shfl_xor_sync(0xffffffffu, f6, d);
        f7 += __shfl_xor_sync(0xffffffffu, f7, d);
    }

    if (g == 0) {
        float* orow = out + ((size_t)b * N_NODES + n) * C + l8 * 8;
        *(float4*)(orow)     = make_float4(f0, f1, f2, f3);
        *(float4*)(orow + 4) = make_float4(f4, f5, f6, f7);
    }
}

// ---------------------------------------------------------------------------
extern "C" void kernel_launch(void* const* d_in, const int* in_sizes, int n_in,
                              void* d_out, int out_size) {
    const float* x    = (const float*)d_in[0];
    const int*   ei   = (const int*)d_in[1];
    const float* fdo  = (const float*)d_in[2];
    const float* flux = (const float*)d_in[3];
    const float* Wc   = (const float*)d_in[4];
    const float* Wd   = (const float*)d_in[5];
    const float* bias = (const float*)d_in[6];
    float* out = (float*)d_out;

    static cudaStream_t s2 = nullptr;
    static cudaEvent_t evFork = nullptr, evJoin = nullptr;
    if (!s2) {
        cudaStreamCreateWithFlags(&s2, cudaStreamNonBlocking);
        cudaEventCreateWithFlags(&evFork, cudaEventDisableTiming);
        cudaEventCreateWithFlags(&evJoin, cudaEventDisableTiming);
    }

    cudaEventRecord(evFork, 0);
    cudaStreamWaitEvent(s2, evFork, 0);
    gemm_kernel<<<2960, 256, 0, s2>>>(x, Wc, Wd);
    cudaEventRecord(evJoin, s2);

    detect_zero_kernel<<<NBLK, 256>>>((const unsigned int*)ei);
    hist_kernel<<<(N_EDGES / 4 + 255) / 256, 256>>>(ei);
    ni_kernel<<<NBLK, 256>>>(flux);
    fill_kernel<<<(N_EDGES / 2 + 255) / 256, 256>>>(ei, fdo);

    cudaStreamWaitEvent(0, evJoin, 0);
    gather_kernel<<<(BATCH * N_NODES * 32 + 127) / 128, 128>>>(bias, out);
}